// round 1
// baseline (speedup 1.0000x reference)
#include <cuda_runtime.h>
#include <cstdint>
#include <math.h>

#define BB 64
#define HH 256
#define WW 256
#define HWSZ 65536           // H*W
#define NTOT 4194304         // B*H*W

// Output layout (concatenated, reference return order):
// uifft [B,2,H,W] @ 0          (8388608)
// cabs  [B,1,H,W] @ 8388608    (4194304)
// mask  [B,1,H,W] @ 12582912   (4194304)
// fft   [B,2,H,W] @ 16777216   (8388608)
// u_k   [B,2,H,W] @ 25165824   (8388608)
#define OFF_UIFFT 0
#define OFF_ABS   8388608
#define OFF_MASK  12582912
#define OFF_FFT   16777216
#define OFF_UK    25165824

__device__ double g_partial[256];
__device__ float  g_r, g_beta;
__device__ int    g_le;

// ---------------- Threefry-2x32-20 (exact jax) ----------------
__host__ __device__ __forceinline__ unsigned rotl32(unsigned v, int d) {
    return (v << d) | (v >> (32 - d));
}

__host__ __device__ inline void threefry2x32(unsigned k0, unsigned k1,
                                             unsigned c0, unsigned c1,
                                             unsigned& o0, unsigned& o1) {
    unsigned ks2 = k0 ^ k1 ^ 0x1BD11BDAu;
    unsigned x0 = c0 + k0;
    unsigned x1 = c1 + k1;
#define TF_R(r) { x0 += x1; x1 = rotl32(x1, r); x1 ^= x0; }
    TF_R(13) TF_R(15) TF_R(26) TF_R(6)
    x0 += k1;  x1 += ks2 + 1u;
    TF_R(17) TF_R(29) TF_R(16) TF_R(24)
    x0 += ks2; x1 += k0 + 2u;
    TF_R(13) TF_R(15) TF_R(26) TF_R(6)
    x0 += k0;  x1 += k1 + 3u;
    TF_R(17) TF_R(29) TF_R(16) TF_R(24)
    x0 += k1;  x1 += ks2 + 4u;
    TF_R(13) TF_R(15) TF_R(26) TF_R(6)
    x0 += ks2; x1 += k0 + 5u;
#undef TF_R
    o0 = x0; o1 = x1;
}

// ---------------- XLA-exact sigmoid pieces ----------------
// XLA lowers logistic(x) -> 0.5 + 0.5*tanh(0.5*x); tanh f32 is the
// Eigen/XLA rational approximation (llvm_ir::EmitFastTanh).
__device__ __forceinline__ float tanh_xla(float x) {
    float ax = fabsf(x);
    float xc = fminf(fmaxf(x, -7.90531110763549805f), 7.90531110763549805f);
    float x2 = __fmul_rn(xc, xc);
    float p = -2.76076847742355e-16f;
    p = fmaf(p, x2, 2.00018790482477e-13f);
    p = fmaf(p, x2, -8.60467152213735e-11f);
    p = fmaf(p, x2, 5.12229709037114e-08f);
    p = fmaf(p, x2, 1.48572235717979e-05f);
    p = fmaf(p, x2, 6.37261928875436e-04f);
    p = fmaf(p, x2, 4.89352455891786e-03f);
    p = __fmul_rn(p, xc);
    float q = 1.19825839466702e-06f;
    q = fmaf(q, x2, 1.18534705686654e-04f);
    q = fmaf(q, x2, 2.26843463243900e-03f);
    q = fmaf(q, x2, 4.89352518554385e-03f);
    float r = __fdiv_rn(p, q);
    return (ax < 0.0004f) ? x : r;
}

__device__ __forceinline__ float prob1_of(float wv) {
    float arg = __fmul_rn(0.5f, __fmul_rn(5.0f, wv));
    float t = tanh_xla(arg);
    return __fadd_rn(0.5f, __fmul_rn(0.5f, t));
}

// ---------------- reduction: xbar = mean(prob1) over H*W ----------------
__global__ void k_reduce(const float* __restrict__ w) {
    __shared__ double sd[256];
    int t = threadIdx.x;
    int idx = blockIdx.x * 256 + t;
    sd[t] = (double)prob1_of(w[idx]);
    __syncthreads();
    for (int s = 128; s > 0; s >>= 1) {
        if (t < s) sd[t] += sd[t + s];
        __syncthreads();
    }
    if (t == 0) g_partial[blockIdx.x] = sd[0];
}

__global__ void k_final() {
    __shared__ double sd[256];
    int t = threadIdx.x;
    sd[t] = g_partial[t];
    __syncthreads();
    for (int s = 128; s > 0; s >>= 1) {
        if (t < s) sd[t] += sd[t + s];
        __syncthreads();
    }
    if (t == 0) {
        float xbar = (float)(sd[0] / 65536.0);
        g_r    = __fdiv_rn(0.125f, xbar);
        g_beta = __fdiv_rn(0.875f, __fsub_rn(1.0f, xbar));
        g_le   = (g_r < 1.0f) ? 1 : 0;
    }
}

// ---------------- mask generation ----------------
__global__ void k_mask(const float* __restrict__ w, float* __restrict__ mask,
                       unsigned sk0, unsigned sk1) {
    unsigned i = blockIdx.x * 256u + threadIdx.x;   // 0 .. NTOT-1
    float wv = w[i & (HWSZ - 1)];
    float p1 = prob1_of(wv);
    float prob2;
    if (g_le) prob2 = __fmul_rn(p1, g_r);
    else      prob2 = __fsub_rn(1.0f, __fmul_rn(__fsub_rn(1.0f, p1), g_beta));
    unsigned o0, o1;
    threefry2x32(sk0, sk1, 0u, i, o0, o1);
    unsigned bits = o0 ^ o1;                         // partitionable 32-bit path
    float u = __uint_as_float((bits >> 9) | 0x3f800000u) - 1.0f;
    mask[i] = (prob2 > u) ? 1.0f : 0.0f;
}

// ---------------- FFT helpers ----------------
__device__ __forceinline__ unsigned brev8(unsigned v) { return __brev(v) >> 24; }

// 256-pt FFT, 128 threads, data in smem (natural-order output, input bit-reversed)
template <int SIGN>
__device__ __forceinline__ void fft256_128t(float* re, float* im, int t) {
#pragma unroll
    for (int s = 1; s <= 8; s++) {
        __syncthreads();
        int half = 1 << (s - 1);
        int pos = t & (half - 1);
        int i0 = ((t >> (s - 1)) << s) + pos;
        int i1 = i0 + half;
        float sn, cs;
        sincospif((float)SIGN * (float)pos / (float)half, &sn, &cs);
        float xr = re[i1], xi = im[i1];
        float tr = cs * xr - sn * xi;
        float ti = cs * xi + sn * xr;
        float ur = re[i0], ui = im[i0];
        re[i0] = ur + tr; im[i0] = ui + ti;
        re[i1] = ur - tr; im[i1] = ui - ti;
    }
    __syncthreads();
}

// Row forward FFT: real x -> complex, write into fft region
__global__ void k_row_fwd(const float* __restrict__ x, float* __restrict__ fftreg) {
    __shared__ float re[256], im[256];
    int t = threadIdx.x;                 // 128
    int h = blockIdx.x, b = blockIdx.y;
    const float* xp = x + (size_t)b * HWSZ + (size_t)h * WW;
    re[brev8(t)] = xp[t];        im[brev8(t)] = 0.0f;
    re[brev8(t + 128)] = xp[t + 128]; im[brev8(t + 128)] = 0.0f;
    fft256_128t<-1>(re, im, t);
    float* fr = fftreg + (size_t)b * 2 * HWSZ + (size_t)h * WW;
    float* fi = fr + HWSZ;
    fr[t] = re[t]; fr[t + 128] = re[t + 128];
    fi[t] = im[t]; fi[t + 128] = im[t + 128];
}

#define SP 17   // smem pitch for 16-column tiles

// Column FFT over h, 16 columns per CTA, 256 threads.
// FWD: in-place on fft region + write u_k = fft*mask.
__global__ void k_col_fwd(float* __restrict__ fftreg, const float* __restrict__ mask,
                          float* __restrict__ ukreg) {
    __shared__ float sre[256 * SP], sim[256 * SP];
    int t = threadIdx.x;
    int b = blockIdx.y;
    int c0 = blockIdx.x * 16;
    int cl = t & 15, rs = t >> 4;
    float* fr = fftreg + (size_t)b * 2 * HWSZ;
    float* fi = fr + HWSZ;
#pragma unroll
    for (int k = 0; k < 16; k++) {
        int row = k * 16 + rs;
        int br = brev8(row);
        sre[br * SP + cl] = fr[row * WW + c0 + cl];
        sim[br * SP + cl] = fi[row * WW + c0 + cl];
    }
#pragma unroll
    for (int s = 1; s <= 8; s++) {
        __syncthreads();
        int half = 1 << (s - 1);
#pragma unroll
        for (int k = 0; k < 8; k++) {
            int j = k * 16 + rs;
            int pos = j & (half - 1);
            int i0 = ((j >> (s - 1)) << s) + pos;
            int i1 = i0 + half;
            float sn, cs;
            sincospif(-(float)pos / (float)half, &sn, &cs);
            int a0 = i0 * SP + cl, a1 = i1 * SP + cl;
            float xr = sre[a1], xi = sim[a1];
            float tr = cs * xr - sn * xi;
            float ti = cs * xi + sn * xr;
            float ur = sre[a0], ui = sim[a0];
            sre[a0] = ur + tr; sim[a0] = ui + ti;
            sre[a1] = ur - tr; sim[a1] = ui - ti;
        }
    }
    __syncthreads();
    float* ur_ = ukreg + (size_t)b * 2 * HWSZ;
    float* ui_ = ur_ + HWSZ;
    const float* mb = mask + (size_t)b * HWSZ;
#pragma unroll
    for (int k = 0; k < 16; k++) {
        int row = k * 16 + rs;
        int g = row * WW + c0 + cl;
        float vr = sre[row * SP + cl], vi = sim[row * SP + cl];
        float m = mb[g];
        fr[g] = vr; fi[g] = vi;
        ur_[g] = vr * m; ui_[g] = vi * m;
    }
}

// Column inverse FFT over h: read u_k, write (scaled 1/256) into uifft region
__global__ void k_col_inv(const float* __restrict__ ukreg, float* __restrict__ dst) {
    __shared__ float sre[256 * SP], sim[256 * SP];
    int t = threadIdx.x;
    int b = blockIdx.y;
    int c0 = blockIdx.x * 16;
    int cl = t & 15, rs = t >> 4;
    const float* fr = ukreg + (size_t)b * 2 * HWSZ;
    const float* fi = fr + HWSZ;
#pragma unroll
    for (int k = 0; k < 16; k++) {
        int row = k * 16 + rs;
        int br = brev8(row);
        sre[br * SP + cl] = fr[row * WW + c0 + cl];
        sim[br * SP + cl] = fi[row * WW + c0 + cl];
    }
#pragma unroll
    for (int s = 1; s <= 8; s++) {
        __syncthreads();
        int half = 1 << (s - 1);
#pragma unroll
        for (int k = 0; k < 8; k++) {
            int j = k * 16 + rs;
            int pos = j & (half - 1);
            int i0 = ((j >> (s - 1)) << s) + pos;
            int i1 = i0 + half;
            float sn, cs;
            sincospif((float)pos / (float)half, &sn, &cs);
            int a0 = i0 * SP + cl, a1 = i1 * SP + cl;
            float xr = sre[a1], xi = sim[a1];
            float tr = cs * xr - sn * xi;
            float ti = cs * xi + sn * xr;
            float ur = sre[a0], ui = sim[a0];
            sre[a0] = ur + tr; sim[a0] = ui + ti;
            sre[a1] = ur - tr; sim[a1] = ui - ti;
        }
    }
    __syncthreads();
    float* dr = dst + (size_t)b * 2 * HWSZ;
    float* di = dr + HWSZ;
    const float sc = 1.0f / 256.0f;
#pragma unroll
    for (int k = 0; k < 16; k++) {
        int row = k * 16 + rs;
        int g = row * WW + c0 + cl;
        dr[g] = sre[row * SP + cl] * sc;
        di[g] = sim[row * SP + cl] * sc;
    }
}

// Row inverse FFT (in place on uifft region) + complex abs
__global__ void k_row_inv(float* __restrict__ uifft, float* __restrict__ cabs) {
    __shared__ float re[256], im[256];
    int t = threadIdx.x;                 // 128
    int h = blockIdx.x, b = blockIdx.y;
    float* fr = uifft + (size_t)b * 2 * HWSZ + (size_t)h * WW;
    float* fi = fr + HWSZ;
    re[brev8(t)] = fr[t];         im[brev8(t)] = fi[t];
    re[brev8(t + 128)] = fr[t + 128]; im[brev8(t + 128)] = fi[t + 128];
    fft256_128t<1>(re, im, t);
    const float sc = 1.0f / 256.0f;
    float* ap = cabs + (size_t)b * HWSZ + (size_t)h * WW;
#pragma unroll
    for (int q = 0; q < 2; q++) {
        int i = t + q * 128;
        float vr = re[i] * sc, vi = im[i] * sc;
        fr[i] = vr; fi[i] = vi;
        ap[i] = sqrtf(vr * vr + vi * vi);
    }
}

extern "C" void kernel_launch(void* const* d_in, const int* in_sizes, int n_in,
                              void* d_out, int out_size) {
    const float* x = (const float*)d_in[0];
    const float* w = (const float*)d_in[1];
    if (n_in >= 2 && in_sizes[0] == HWSZ) {  // defensive: identify by size
        x = (const float*)d_in[1];
        w = (const float*)d_in[0];
    }
    float* out   = (float*)d_out;
    float* uifft = out + OFF_UIFFT;
    float* cabs  = out + OFF_ABS;
    float* mask  = out + OFF_MASK;
    float* fft   = out + OFF_FFT;
    float* uk    = out + OFF_UK;

    // sub-key from jax.random.split(key(42)) (partitionable/foldlike):
    // sub = threefry((0,42), counter=(0,1))
    unsigned sk0, sk1;
    threefry2x32(0u, 42u, 0u, 1u, sk0, sk1);

    k_reduce<<<256, 256>>>(w);
    k_final<<<1, 256>>>();
    k_mask<<<NTOT / 256, 256>>>(w, mask, sk0, sk1);
    k_row_fwd<<<dim3(HH, BB), 128>>>(x, fft);
    k_col_fwd<<<dim3(WW / 16, BB), 256>>>(fft, mask, uk);
    k_col_inv<<<dim3(WW / 16, BB), 256>>>(uk, uifft);
    k_row_inv<<<dim3(HH, BB), 128>>>(uifft, cabs);
}